// round 1
// baseline (speedup 1.0000x reference)
#include <cuda_runtime.h>
#include <math.h>

#define SQ   4096
#define EMB  1152
#define NH   16
#define HD   72
#define HALF 36
#define NSEG 8
#define QKV3 (3*EMB)

#define BQ 64
#define BK 64
#define PS_STRIDE 68

static __device__ float g_qkv[(size_t)SQ * QKV3];   // (S, 3E) scratch
static __device__ float g_attn[(size_t)SQ * EMB];   // (S, E) attention output

// ---------------------------------------------------------------------------
// SGEMM: C[M,N] = A[M,K] * B[N,K]^T + bias[N].  A,B row-major (both K-major).
// BM=BN=128, BK=16, 256 threads, 8x8 micro-tile. All dims divisible.
// ---------------------------------------------------------------------------
template<int MM, int NN, int KK>
__global__ __launch_bounds__(256)
void sgemm_nt(const float* __restrict__ A, const float* __restrict__ B,
              const float* __restrict__ bias, float* __restrict__ C)
{
    __shared__ float As[16][132];
    __shared__ float Bs[16][132];

    const int bm  = blockIdx.y * 128;
    const int bn  = blockIdx.x * 128;
    const int tid = threadIdx.x;
    const int tx  = tid & 15;
    const int ty  = tid >> 4;
    const int lrow = tid >> 2;          // 0..63
    const int lcol = (tid & 3) << 2;    // 0,4,8,12

    float acc[8][8];
    #pragma unroll
    for (int i = 0; i < 8; i++)
        #pragma unroll
        for (int j = 0; j < 8; j++) acc[i][j] = 0.0f;

    const float* Aptr = A + (size_t)(bm + lrow) * KK + lcol;
    const float* Bptr = B + (size_t)(bn + lrow) * KK + lcol;

    for (int k0 = 0; k0 < KK; k0 += 16) {
        float4 a0 = *(const float4*)(Aptr + k0);
        float4 a1 = *(const float4*)(Aptr + (size_t)64 * KK + k0);
        float4 b0 = *(const float4*)(Bptr + k0);
        float4 b1 = *(const float4*)(Bptr + (size_t)64 * KK + k0);

        As[lcol+0][lrow]    = a0.x; As[lcol+1][lrow]    = a0.y;
        As[lcol+2][lrow]    = a0.z; As[lcol+3][lrow]    = a0.w;
        As[lcol+0][lrow+64] = a1.x; As[lcol+1][lrow+64] = a1.y;
        As[lcol+2][lrow+64] = a1.z; As[lcol+3][lrow+64] = a1.w;
        Bs[lcol+0][lrow]    = b0.x; Bs[lcol+1][lrow]    = b0.y;
        Bs[lcol+2][lrow]    = b0.z; Bs[lcol+3][lrow]    = b0.w;
        Bs[lcol+0][lrow+64] = b1.x; Bs[lcol+1][lrow+64] = b1.y;
        Bs[lcol+2][lrow+64] = b1.z; Bs[lcol+3][lrow+64] = b1.w;
        __syncthreads();

        #pragma unroll
        for (int k = 0; k < 16; k++) {
            float4 x0 = *(const float4*)&As[k][ty*8];
            float4 x1 = *(const float4*)&As[k][ty*8+4];
            float4 y0 = *(const float4*)&Bs[k][tx*8];
            float4 y1 = *(const float4*)&Bs[k][tx*8+4];
            float a[8] = {x0.x,x0.y,x0.z,x0.w,x1.x,x1.y,x1.z,x1.w};
            float b[8] = {y0.x,y0.y,y0.z,y0.w,y1.x,y1.y,y1.z,y1.w};
            #pragma unroll
            for (int i = 0; i < 8; i++)
                #pragma unroll
                for (int j = 0; j < 8; j++)
                    acc[i][j] = fmaf(a[i], b[j], acc[i][j]);
        }
        __syncthreads();
    }

    #pragma unroll
    for (int i = 0; i < 8; i++) {
        const size_t row = (size_t)(bm + ty*8 + i);
        #pragma unroll
        for (int j = 0; j < 8; j++) {
            const int col = bn + tx*8 + j;
            C[row * NN + col] = acc[i][j] + bias[col];
        }
    }
}

// ---------------------------------------------------------------------------
// RoPE in-place on q,k halves of g_qkv.
// pair index -> (s, qk, h, d) with d in [0, HALF)
// ---------------------------------------------------------------------------
__global__ __launch_bounds__(256)
void rope_kernel(const float* __restrict__ cosT, const float* __restrict__ sinT)
{
    int idx = blockIdx.x * blockDim.x + threadIdx.x;
    const int total = SQ * 2 * NH * HALF;
    if (idx >= total) return;
    int d  = idx % HALF;
    int h  = (idx / HALF) % NH;
    int qk = (idx / (HALF * NH)) & 1;
    int s  = idx / (HALF * NH * 2);

    float* base = g_qkv + (size_t)s * QKV3 + qk * EMB + h * HD;
    float x1 = base[d];
    float x2 = base[d + HALF];
    float c  = cosT[(size_t)s * HD + d];
    float sn = sinT[(size_t)s * HD + d];
    base[d]        = x1 * c - x2 * sn;
    base[d + HALF] = x2 * c + x1 * sn;
}

// ---------------------------------------------------------------------------
// Block-diagonal varlen flash attention.
// grid = (SQ/BQ, NH), 256 threads. Dynamic smem:
//   Qt[72][64] (swizzled), Kt[72][64] (swizzled), Vs[64][72], Ps[64][68],
//   segq[64], segk[64], cus[NSEG+1]
// ---------------------------------------------------------------------------
#define ATTN_SMEM_BYTES ((HD*64*2 + 64*HD + 64*PS_STRIDE) * 4 + (64 + 64 + 16) * 4)

__global__ __launch_bounds__(256)
void attn_kernel(const float* __restrict__ qkv, const int* __restrict__ cu,
                 float* __restrict__ out)
{
    extern __shared__ float sm[];
    float* Qt = sm;                     // [72][64] swizzled
    float* Kt = Qt + HD * 64;           // [72][64] swizzled
    float* Vs = Kt + HD * 64;           // [64][72]
    float* Ps = Vs + 64 * HD;           // [64][PS_STRIDE]
    int* segq = (int*)(Ps + 64 * PS_STRIDE);
    int* segk = segq + 64;
    int* cus  = segk + 64;

    const int tid = threadIdx.x;
    const int tx  = tid & 15;
    const int ty  = tid >> 4;
    const int h   = blockIdx.y;
    const int q0  = blockIdx.x * BQ;

    if (tid <= NSEG) cus[tid] = cu[tid];
    __syncthreads();

    if (tid < BQ) {
        int p = q0 + tid;
        int s = 0;
        #pragma unroll
        for (int i = 1; i <= NSEG; i++) s += (p >= cus[i]);
        segq[tid] = s;
    }
    // Load Q tile, transposed + swizzled
    #pragma unroll
    for (int it = 0; it < (BQ * HD) / 256; it++) {
        int idx = tid + it * 256;
        int d = idx % HD, r = idx / HD;
        float v = qkv[(size_t)(q0 + r) * QKV3 + h * HD + d];
        int c = ((((r >> 2) ^ (d & 15)) << 2) | (r & 3));
        Qt[d * 64 + c] = v;
    }
    __syncthreads();

    int sq[4];
    #pragma unroll
    for (int i = 0; i < 4; i++) sq[i] = segq[ty*4 + i];
    const int k_lo = cus[segq[0]];
    const int k_hi = cus[segq[BQ-1] + 1];

    float m[4], l[4], acc[4][5];
    #pragma unroll
    for (int i = 0; i < 4; i++) {
        m[i] = -1e30f; l[i] = 0.0f;
        #pragma unroll
        for (int j = 0; j < 5; j++) acc[i][j] = 0.0f;
    }
    const float scale = 0.11785113019775793f;  // 1/sqrt(72)

    for (int kk0 = k_lo; kk0 < k_hi; kk0 += BK) {
        // Load K (transposed+swizzled) and V (natural)
        #pragma unroll
        for (int it = 0; it < (BK * HD) / 256; it++) {
            int idx = tid + it * 256;
            int d = idx % HD, c = idx / HD;
            int key = kk0 + c;
            float kv = 0.0f, vv = 0.0f;
            if (key < k_hi) {
                const float* row = qkv + (size_t)key * QKV3 + h * HD + d;
                kv = row[EMB];
                vv = row[2 * EMB];
            }
            int cc = ((((c >> 2) ^ (d & 15)) << 2) | (c & 3));
            Kt[d * 64 + cc] = kv;
            Vs[c * HD + d]  = vv;
        }
        if (tid < BK) {
            int key = kk0 + tid;
            int s = -1;
            if (key < k_hi) {
                s = 0;
                #pragma unroll
                for (int i = 1; i <= NSEG; i++) s += (key >= cus[i]);
            }
            segk[tid] = s;
        }
        __syncthreads();

        // S = Q K^T  (thread owns rows ty*4+i, cols tx*4+j)
        float sc[4][4];
        #pragma unroll
        for (int i = 0; i < 4; i++)
            #pragma unroll
            for (int j = 0; j < 4; j++) sc[i][j] = 0.0f;

        #pragma unroll 8
        for (int d = 0; d < HD; d++) {
            int sw = d & 15;
            float4 a = ((const float4*)(Qt + d * 64))[ty ^ sw];
            float4 b = ((const float4*)(Kt + d * 64))[tx ^ sw];
            float av[4] = {a.x, a.y, a.z, a.w};
            float bv[4] = {b.x, b.y, b.z, b.w};
            #pragma unroll
            for (int i = 0; i < 4; i++)
                #pragma unroll
                for (int j = 0; j < 4; j++)
                    sc[i][j] = fmaf(av[i], bv[j], sc[i][j]);
        }

        int sk[4];
        #pragma unroll
        for (int j = 0; j < 4; j++) sk[j] = segk[tx*4 + j];

        // scale + mask + row max
        float mloc[4];
        #pragma unroll
        for (int i = 0; i < 4; i++) {
            mloc[i] = -1e30f;
            #pragma unroll
            for (int j = 0; j < 4; j++) {
                sc[i][j] = (sk[j] == sq[i]) ? sc[i][j] * scale : -1e30f;
                mloc[i] = fmaxf(mloc[i], sc[i][j]);
            }
        }
        #pragma unroll
        for (int o = 8; o >= 1; o >>= 1)
            #pragma unroll
            for (int i = 0; i < 4; i++)
                mloc[i] = fmaxf(mloc[i], __shfl_xor_sync(0xffffffffu, mloc[i], o, 16));

        float fac[4], rs[4];
        #pragma unroll
        for (int i = 0; i < 4; i++) {
            float mn = fmaxf(m[i], mloc[i]);
            fac[i] = __expf(m[i] - mn);
            m[i] = mn;
            float r = 0.0f;
            #pragma unroll
            for (int j = 0; j < 4; j++) {
                float p = (sc[i][j] > -1e29f) ? __expf(sc[i][j] - mn) : 0.0f;
                sc[i][j] = p;
                r += p;
            }
            rs[i] = r;
        }
        #pragma unroll
        for (int o = 8; o >= 1; o >>= 1)
            #pragma unroll
            for (int i = 0; i < 4; i++)
                rs[i] += __shfl_xor_sync(0xffffffffu, rs[i], o, 16);

        #pragma unroll
        for (int i = 0; i < 4; i++) {
            l[i] = l[i] * fac[i] + rs[i];
            #pragma unroll
            for (int j = 0; j < 5; j++) acc[i][j] *= fac[i];
        }

        // stage P
        #pragma unroll
        for (int i = 0; i < 4; i++)
            #pragma unroll
            for (int j = 0; j < 4; j++)
                Ps[(ty*4 + i) * PS_STRIDE + tx*4 + j] = sc[i][j];
        __syncthreads();

        // O += P V   (thread owns rows ty*4+i, head-dims tx+16*jj)
        #pragma unroll 8
        for (int c = 0; c < BK; c++) {
            float p[4];
            #pragma unroll
            for (int i = 0; i < 4; i++) p[i] = Ps[(ty*4 + i) * PS_STRIDE + c];
            #pragma unroll
            for (int jj = 0; jj < 5; jj++) {
                int d = tx + 16 * jj;
                float v = (d < HD) ? Vs[c * HD + d] : 0.0f;
                #pragma unroll
                for (int i = 0; i < 4; i++)
                    acc[i][jj] = fmaf(p[i], v, acc[i][jj]);
            }
        }
        __syncthreads();
    }

    // normalize + write
    #pragma unroll
    for (int i = 0; i < 4; i++) {
        float inv = 1.0f / l[i];
        size_t row = (size_t)(q0 + ty*4 + i);
        #pragma unroll
        for (int jj = 0; jj < 5; jj++) {
            int d = tx + 16 * jj;
            if (d < HD) out[row * EMB + h * HD + d] = acc[i][jj] * inv;
        }
    }
}

// ---------------------------------------------------------------------------
extern "C" void kernel_launch(void* const* d_in, const int* in_sizes, int n_in,
                              void* d_out, int out_size)
{
    const float* hidden = (const float*)d_in[0];
    const int*   cu     = (const int*)  d_in[1];
    const float* cosT   = (const float*)d_in[2];
    const float* sinT   = (const float*)d_in[3];
    const float* w_qkv  = (const float*)d_in[4];
    const float* b_qkv  = (const float*)d_in[5];
    const float* w_out  = (const float*)d_in[6];
    const float* b_out  = (const float*)d_in[7];
    float* out = (float*)d_out;

    void* p_qkv = nullptr;
    void* p_attn = nullptr;
    cudaGetSymbolAddress(&p_qkv, g_qkv);
    cudaGetSymbolAddress(&p_attn, g_attn);
    float* qkv  = (float*)p_qkv;
    float* attn = (float*)p_attn;

    // 1) QKV projection
    dim3 g1(QKV3 / 128, SQ / 128);
    sgemm_nt<SQ, QKV3, EMB><<<g1, 256>>>(hidden, w_qkv, b_qkv, qkv);

    // 2) RoPE on q,k in place
    const int total = SQ * 2 * NH * HALF;
    rope_kernel<<<(total + 255) / 256, 256>>>(cosT, sinT);

    // 3) varlen block-diagonal attention
    cudaFuncSetAttribute(attn_kernel, cudaFuncAttributeMaxDynamicSharedMemorySize,
                         ATTN_SMEM_BYTES);
    attn_kernel<<<dim3(SQ / BQ, NH), 256, ATTN_SMEM_BYTES>>>(qkv, cu, attn);

    // 4) output projection
    dim3 g2(EMB / 128, SQ / 128);
    sgemm_nt<SQ, EMB, EMB><<<g2, 256>>>(attn, w_out, b_out, out);
}

// round 3
// speedup vs baseline: 1.5826x; 1.5826x over previous
#include <cuda_runtime.h>
#include <math.h>

#define SQ   4096
#define EMB  1152
#define NH   16
#define HD   72
#define HALF 36
#define NSEG 8
#define QKV3 (3*EMB)

#define BQ 64
#define BK 64
#define PS_STRIDE 68

static __device__ float g_qkv[(size_t)SQ * QKV3];   // (S, 3E) scratch
static __device__ float g_attn[(size_t)SQ * EMB];   // (S, E) attention output

// ---------------------------------------------------------------------------
// TF32 helpers
// ---------------------------------------------------------------------------
__device__ __forceinline__ unsigned f2tf32(float x) {
    unsigned r;
    asm("cvt.rna.tf32.f32 %0, %1;" : "=r"(r) : "f"(x));
    return r;
}

__device__ __forceinline__ void mma_tf32(float c[4],
                                         unsigned a0, unsigned a1, unsigned a2, unsigned a3,
                                         unsigned b0, unsigned b1) {
    asm("mma.sync.aligned.m16n8k8.row.col.f32.tf32.tf32.f32 "
        "{%0,%1,%2,%3}, {%4,%5,%6,%7}, {%8,%9}, {%0,%1,%2,%3};"
        : "+f"(c[0]), "+f"(c[1]), "+f"(c[2]), "+f"(c[3])
        : "r"(a0), "r"(a1), "r"(a2), "r"(a3), "r"(b0), "r"(b1));
}

// ---------------------------------------------------------------------------
// TF32 tensor-core GEMM: C[M,N] = A[M,K] * B[N,K]^T + bias[N]
// BM=BN=128, BK=16, 256 threads (8 warps, 2x4), warp tile 64x32.
// Smem layout [k][m] with stride 136 + XOR swizzle: conflict-free STS and LDS.
// ---------------------------------------------------------------------------
template<int NN, int KK>
__global__ __launch_bounds__(256)
void gemm_tf32(const float* __restrict__ A, const float* __restrict__ B,
               const float* __restrict__ bias, float* __restrict__ C)
{
    __shared__ unsigned As[16][136];
    __shared__ unsigned Bs[16][136];

    const int bm   = blockIdx.y * 128;
    const int bn   = blockIdx.x * 128;
    const int tid  = threadIdx.x;
    const int warp = tid >> 5;
    const int lane = tid & 31;
    const int wm   = warp >> 2;        // 0..1
    const int wn   = warp & 3;         // 0..3
    const int r    = lane >> 2;        // 0..7
    const int c    = lane & 3;         // 0..3
    const int lrow = tid >> 2;         // 0..63
    const int lcol = (tid & 3) << 2;   // 0,4,8,12

    float acc[4][4][4];
    #pragma unroll
    for (int mt = 0; mt < 4; mt++)
        #pragma unroll
        for (int nt = 0; nt < 4; nt++)
            #pragma unroll
            for (int i = 0; i < 4; i++) acc[mt][nt][i] = 0.0f;

    const float* Aptr = A + (size_t)(bm + lrow) * KK + lcol;
    const float* Bptr = B + (size_t)(bn + lrow) * KK + lcol;

    for (int k0 = 0; k0 < KK; k0 += 16) {
        float4 ga0 = *(const float4*)(Aptr + k0);
        float4 ga1 = *(const float4*)(Aptr + (size_t)64 * KK + k0);
        float4 gb0 = *(const float4*)(Bptr + k0);
        float4 gb1 = *(const float4*)(Bptr + (size_t)64 * KK + k0);
        float av0[4] = {ga0.x, ga0.y, ga0.z, ga0.w};
        float av1[4] = {ga1.x, ga1.y, ga1.z, ga1.w};
        float bv0[4] = {gb0.x, gb0.y, gb0.z, gb0.w};
        float bv1[4] = {gb1.x, gb1.y, gb1.z, gb1.w};

        #pragma unroll
        for (int j = 0; j < 4; j++) {
            int k = lcol + j;
            int s = ((k >> 2) & 3) << 3;
            As[k][lrow ^ s]        = f2tf32(av0[j]);
            As[k][(lrow + 64) ^ s] = f2tf32(av1[j]);
            Bs[k][lrow ^ s]        = f2tf32(bv0[j]);
            Bs[k][(lrow + 64) ^ s] = f2tf32(bv1[j]);
        }
        __syncthreads();

        #pragma unroll
        for (int kc = 0; kc < 16; kc += 8) {
            const int s0 = ((kc >> 2) & 3) << 3;        // swizzle for rows kc..kc+3
            const int s1 = (((kc >> 2) + 1) & 3) << 3;  // swizzle for rows kc+4..kc+7

            unsigned af[4][4], bf[4][2];
            #pragma unroll
            for (int mt = 0; mt < 4; mt++) {
                const int mb = wm * 64 + mt * 16;
                af[mt][0] = As[kc + c][(mb + r) ^ s0];
                af[mt][1] = As[kc + c][(mb + r + 8) ^ s0];
                af[mt][2] = As[kc + c + 4][(mb + r) ^ s1];
                af[mt][3] = As[kc + c + 4][(mb + r + 8) ^ s1];
            }
            #pragma unroll
            for (int nt = 0; nt < 4; nt++) {
                const int nb = wn * 32 + nt * 8;
                bf[nt][0] = Bs[kc + c][(nb + r) ^ s0];
                bf[nt][1] = Bs[kc + c + 4][(nb + r) ^ s1];
            }
            #pragma unroll
            for (int mt = 0; mt < 4; mt++)
                #pragma unroll
                for (int nt = 0; nt < 4; nt++)
                    mma_tf32(acc[mt][nt], af[mt][0], af[mt][1], af[mt][2], af[mt][3],
                             bf[nt][0], bf[nt][1]);
        }
        __syncthreads();
    }

    // epilogue: c0=(r,2c) c1=(r,2c+1) c2=(r+8,2c) c3=(r+8,2c+1)
    #pragma unroll
    for (int nt = 0; nt < 4; nt++) {
        const int col = bn + wn * 32 + nt * 8 + 2 * c;
        const float2 bb = *(const float2*)(bias + col);
        #pragma unroll
        for (int mt = 0; mt < 4; mt++) {
            const int row0 = bm + wm * 64 + mt * 16 + r;
            float2 o0 = make_float2(acc[mt][nt][0] + bb.x, acc[mt][nt][1] + bb.y);
            float2 o1 = make_float2(acc[mt][nt][2] + bb.x, acc[mt][nt][3] + bb.y);
            *(float2*)&C[(size_t)row0 * NN + col]       = o0;
            *(float2*)&C[(size_t)(row0 + 8) * NN + col] = o1;
        }
    }
}

// ---------------------------------------------------------------------------
// RoPE in-place on q,k halves of g_qkv.
// ---------------------------------------------------------------------------
__global__ __launch_bounds__(256)
void rope_kernel(const float* __restrict__ cosT, const float* __restrict__ sinT)
{
    int idx = blockIdx.x * blockDim.x + threadIdx.x;
    const int total = SQ * 2 * NH * HALF;
    if (idx >= total) return;
    int d  = idx % HALF;
    int h  = (idx / HALF) % NH;
    int qk = (idx / (HALF * NH)) & 1;
    int s  = idx / (HALF * NH * 2);

    float* base = g_qkv + (size_t)s * QKV3 + qk * EMB + h * HD;
    float x1 = base[d];
    float x2 = base[d + HALF];
    float c  = cosT[(size_t)s * HD + d];
    float sn = sinT[(size_t)s * HD + d];
    base[d]        = x1 * c - x2 * sn;
    base[d + HALF] = x2 * c + x1 * sn;
}

// ---------------------------------------------------------------------------
// Block-diagonal varlen flash attention (unchanged from R1).
// ---------------------------------------------------------------------------
#define ATTN_SMEM_BYTES ((HD*64*2 + 64*HD + 64*PS_STRIDE) * 4 + (64 + 64 + 16) * 4)

__global__ __launch_bounds__(256)
void attn_kernel(const float* __restrict__ qkv, const int* __restrict__ cu,
                 float* __restrict__ out)
{
    extern __shared__ float sm[];
    float* Qt = sm;                     // [72][64] swizzled
    float* Kt = Qt + HD * 64;           // [72][64] swizzled
    float* Vs = Kt + HD * 64;           // [64][72]
    float* Ps = Vs + 64 * HD;           // [64][PS_STRIDE]
    int* segq = (int*)(Ps + 64 * PS_STRIDE);
    int* segk = segq + 64;
    int* cus  = segk + 64;

    const int tid = threadIdx.x;
    const int tx  = tid & 15;
    const int ty  = tid >> 4;
    const int h   = blockIdx.y;
    const int q0  = blockIdx.x * BQ;

    if (tid <= NSEG) cus[tid] = cu[tid];
    __syncthreads();

    if (tid < BQ) {
        int p = q0 + tid;
        int s = 0;
        #pragma unroll
        for (int i = 1; i <= NSEG; i++) s += (p >= cus[i]);
        segq[tid] = s;
    }
    #pragma unroll
    for (int it = 0; it < (BQ * HD) / 256; it++) {
        int idx = tid + it * 256;
        int d = idx % HD, r = idx / HD;
        float v = qkv[(size_t)(q0 + r) * QKV3 + h * HD + d];
        int c = ((((r >> 2) ^ (d & 15)) << 2) | (r & 3));
        Qt[d * 64 + c] = v;
    }
    __syncthreads();

    int sq[4];
    #pragma unroll
    for (int i = 0; i < 4; i++) sq[i] = segq[ty*4 + i];
    const int k_lo = cus[segq[0]];
    const int k_hi = cus[segq[BQ-1] + 1];

    float m[4], l[4], acc[4][5];
    #pragma unroll
    for (int i = 0; i < 4; i++) {
        m[i] = -1e30f; l[i] = 0.0f;
        #pragma unroll
        for (int j = 0; j < 5; j++) acc[i][j] = 0.0f;
    }
    const float scale = 0.11785113019775793f;  // 1/sqrt(72)

    for (int kk0 = k_lo; kk0 < k_hi; kk0 += BK) {
        #pragma unroll
        for (int it = 0; it < (BK * HD) / 256; it++) {
            int idx = tid + it * 256;
            int d = idx % HD, c = idx / HD;
            int key = kk0 + c;
            float kv = 0.0f, vv = 0.0f;
            if (key < k_hi) {
                const float* row = qkv + (size_t)key * QKV3 + h * HD + d;
                kv = row[EMB];
                vv = row[2 * EMB];
            }
            int cc = ((((c >> 2) ^ (d & 15)) << 2) | (c & 3));
            Kt[d * 64 + cc] = kv;
            Vs[c * HD + d]  = vv;
        }
        if (tid < BK) {
            int key = kk0 + tid;
            int s = -1;
            if (key < k_hi) {
                s = 0;
                #pragma unroll
                for (int i = 1; i <= NSEG; i++) s += (key >= cus[i]);
            }
            segk[tid] = s;
        }
        __syncthreads();

        float sc[4][4];
        #pragma unroll
        for (int i = 0; i < 4; i++)
            #pragma unroll
            for (int j = 0; j < 4; j++) sc[i][j] = 0.0f;

        #pragma unroll 8
        for (int d = 0; d < HD; d++) {
            int sw = d & 15;
            float4 a = ((const float4*)(Qt + d * 64))[ty ^ sw];
            float4 b = ((const float4*)(Kt + d * 64))[tx ^ sw];
            float av[4] = {a.x, a.y, a.z, a.w};
            float bv[4] = {b.x, b.y, b.z, b.w};
            #pragma unroll
            for (int i = 0; i < 4; i++)
                #pragma unroll
                for (int j = 0; j < 4; j++)
                    sc[i][j] = fmaf(av[i], bv[j], sc[i][j]);
        }

        int sk[4];
        #pragma unroll
        for (int j = 0; j < 4; j++) sk[j] = segk[tx*4 + j];

        float mloc[4];
        #pragma unroll
        for (int i = 0; i < 4; i++) {
            mloc[i] = -1e30f;
            #pragma unroll
            for (int j = 0; j < 4; j++) {
                sc[i][j] = (sk[j] == sq[i]) ? sc[i][j] * scale : -1e30f;
                mloc[i] = fmaxf(mloc[i], sc[i][j]);
            }
        }
        #pragma unroll
        for (int o = 8; o >= 1; o >>= 1)
            #pragma unroll
            for (int i = 0; i < 4; i++)
                mloc[i] = fmaxf(mloc[i], __shfl_xor_sync(0xffffffffu, mloc[i], o, 16));

        float fac[4], rs[4];
        #pragma unroll
        for (int i = 0; i < 4; i++) {
            float mn = fmaxf(m[i], mloc[i]);
            fac[i] = __expf(m[i] - mn);
            m[i] = mn;
            float r = 0.0f;
            #pragma unroll
            for (int j = 0; j < 4; j++) {
                float p = (sc[i][j] > -1e29f) ? __expf(sc[i][j] - mn) : 0.0f;
                sc[i][j] = p;
                r += p;
            }
            rs[i] = r;
        }
        #pragma unroll
        for (int o = 8; o >= 1; o >>= 1)
            #pragma unroll
            for (int i = 0; i < 4; i++)
                rs[i] += __shfl_xor_sync(0xffffffffu, rs[i], o, 16);

        #pragma unroll
        for (int i = 0; i < 4; i++) {
            l[i] = l[i] * fac[i] + rs[i];
            #pragma unroll
            for (int j = 0; j < 5; j++) acc[i][j] *= fac[i];
        }

        #pragma unroll
        for (int i = 0; i < 4; i++)
            #pragma unroll
            for (int j = 0; j < 4; j++)
                Ps[(ty*4 + i) * PS_STRIDE + tx*4 + j] = sc[i][j];
        __syncthreads();

        #pragma unroll 8
        for (int c = 0; c < BK; c++) {
            float p[4];
            #pragma unroll
            for (int i = 0; i < 4; i++) p[i] = Ps[(ty*4 + i) * PS_STRIDE + c];
            #pragma unroll
            for (int jj = 0; jj < 5; jj++) {
                int d = tx + 16 * jj;
                float v = (d < HD) ? Vs[c * HD + d] : 0.0f;
                #pragma unroll
                for (int i = 0; i < 4; i++)
                    acc[i][jj] = fmaf(p[i], v, acc[i][jj]);
            }
        }
        __syncthreads();
    }

    #pragma unroll
    for (int i = 0; i < 4; i++) {
        float inv = 1.0f / l[i];
        size_t row = (size_t)(q0 + ty*4 + i);
        #pragma unroll
        for (int jj = 0; jj < 5; jj++) {
            int d = tx + 16 * jj;
            if (d < HD) out[row * EMB + h * HD + d] = acc[i][jj] * inv;
        }
    }
}

// ---------------------------------------------------------------------------
extern "C" void kernel_launch(void* const* d_in, const int* in_sizes, int n_in,
                              void* d_out, int out_size)
{
    const float* hidden = (const float*)d_in[0];
    const int*   cu     = (const int*)  d_in[1];
    const float* cosT   = (const float*)d_in[2];
    const float* sinT   = (const float*)d_in[3];
    const float* w_qkv  = (const float*)d_in[4];
    const float* b_qkv  = (const float*)d_in[5];
    const float* w_out  = (const float*)d_in[6];
    const float* b_out  = (const float*)d_in[7];
    float* out = (float*)d_out;

    void* p_qkv = nullptr;
    void* p_attn = nullptr;
    cudaGetSymbolAddress(&p_qkv, g_qkv);
    cudaGetSymbolAddress(&p_attn, g_attn);
    float* qkv  = (float*)p_qkv;
    float* attn = (float*)p_attn;

    // 1) QKV projection (tf32 tensor cores)
    dim3 g1(QKV3 / 128, SQ / 128);
    gemm_tf32<QKV3, EMB><<<g1, 256>>>(hidden, w_qkv, b_qkv, qkv);

    // 2) RoPE on q,k in place
    const int total = SQ * 2 * NH * HALF;
    rope_kernel<<<(total + 255) / 256, 256>>>(cosT, sinT);

    // 3) varlen block-diagonal attention
    cudaFuncSetAttribute(attn_kernel, cudaFuncAttributeMaxDynamicSharedMemorySize,
                         ATTN_SMEM_BYTES);
    attn_kernel<<<dim3(SQ / BQ, NH), 256, ATTN_SMEM_BYTES>>>(qkv, cu, attn);

    // 4) output projection (tf32 tensor cores)
    dim3 g2(EMB / 128, SQ / 128);
    gemm_tf32<EMB, EMB><<<g2, 256>>>(attn, w_out, b_out, out);
}

// round 5
// speedup vs baseline: 2.0385x; 1.2881x over previous
#include <cuda_runtime.h>
#include <math.h>

#define SQ   4096
#define EMB  1152
#define NH   16
#define HD   72
#define HALF 36
#define NSEG 8
#define QKV3 (3*EMB)

#define BQ 64
#define BK 64

#define QSTR 76   // Q/K hi+lo smem stride (floats)
#define VSTR 88   // V smem stride (80 dims incl. pad)
#define PSTR 72   // P^T smem stride

static __device__ float g_qkv[(size_t)SQ * QKV3];   // (S, 3E) scratch
static __device__ float g_attn[(size_t)SQ * EMB];   // (S, E) attention output

// ---------------------------------------------------------------------------
// TF32 helpers
// ---------------------------------------------------------------------------
__device__ __forceinline__ unsigned f2tf32(float x) {
    unsigned r;
    asm("cvt.rna.tf32.f32 %0, %1;" : "=r"(r) : "f"(x));
    return r;
}

__device__ __forceinline__ void mma_tf32(float c[4],
                                         unsigned a0, unsigned a1, unsigned a2, unsigned a3,
                                         unsigned b0, unsigned b1) {
    asm("mma.sync.aligned.m16n8k8.row.col.f32.tf32.tf32.f32 "
        "{%0,%1,%2,%3}, {%4,%5,%6,%7}, {%8,%9}, {%0,%1,%2,%3};"
        : "+f"(c[0]), "+f"(c[1]), "+f"(c[2]), "+f"(c[3])
        : "r"(a0), "r"(a1), "r"(a2), "r"(a3), "r"(b0), "r"(b1));
}

// ---------------------------------------------------------------------------
// TF32 tensor-core GEMM: C[M,N] = A[M,K] * B[N,K]^T + bias[N]  (unchanged)
// ---------------------------------------------------------------------------
template<int NN, int KK>
__global__ __launch_bounds__(256)
void gemm_tf32(const float* __restrict__ A, const float* __restrict__ B,
               const float* __restrict__ bias, float* __restrict__ C)
{
    __shared__ unsigned As[16][136];
    __shared__ unsigned Bs[16][136];

    const int bm   = blockIdx.y * 128;
    const int bn   = blockIdx.x * 128;
    const int tid  = threadIdx.x;
    const int warp = tid >> 5;
    const int lane = tid & 31;
    const int wm   = warp >> 2;
    const int wn   = warp & 3;
    const int r    = lane >> 2;
    const int c    = lane & 3;
    const int lrow = tid >> 2;
    const int lcol = (tid & 3) << 2;

    float acc[4][4][4];
    #pragma unroll
    for (int mt = 0; mt < 4; mt++)
        #pragma unroll
        for (int nt = 0; nt < 4; nt++)
            #pragma unroll
            for (int i = 0; i < 4; i++) acc[mt][nt][i] = 0.0f;

    const float* Aptr = A + (size_t)(bm + lrow) * KK + lcol;
    const float* Bptr = B + (size_t)(bn + lrow) * KK + lcol;

    for (int k0 = 0; k0 < KK; k0 += 16) {
        float4 ga0 = *(const float4*)(Aptr + k0);
        float4 ga1 = *(const float4*)(Aptr + (size_t)64 * KK + k0);
        float4 gb0 = *(const float4*)(Bptr + k0);
        float4 gb1 = *(const float4*)(Bptr + (size_t)64 * KK + k0);
        float av0[4] = {ga0.x, ga0.y, ga0.z, ga0.w};
        float av1[4] = {ga1.x, ga1.y, ga1.z, ga1.w};
        float bv0[4] = {gb0.x, gb0.y, gb0.z, gb0.w};
        float bv1[4] = {gb1.x, gb1.y, gb1.z, gb1.w};

        #pragma unroll
        for (int j = 0; j < 4; j++) {
            int k = lcol + j;
            int s = ((k >> 2) & 3) << 3;
            As[k][lrow ^ s]        = f2tf32(av0[j]);
            As[k][(lrow + 64) ^ s] = f2tf32(av1[j]);
            Bs[k][lrow ^ s]        = f2tf32(bv0[j]);
            Bs[k][(lrow + 64) ^ s] = f2tf32(bv1[j]);
        }
        __syncthreads();

        #pragma unroll
        for (int kc = 0; kc < 16; kc += 8) {
            const int s0 = ((kc >> 2) & 3) << 3;
            const int s1 = (((kc >> 2) + 1) & 3) << 3;

            unsigned af[4][4], bf[4][2];
            #pragma unroll
            for (int mt = 0; mt < 4; mt++) {
                const int mb = wm * 64 + mt * 16;
                af[mt][0] = As[kc + c][(mb + r) ^ s0];
                af[mt][1] = As[kc + c][(mb + r + 8) ^ s0];
                af[mt][2] = As[kc + c + 4][(mb + r) ^ s1];
                af[mt][3] = As[kc + c + 4][(mb + r + 8) ^ s1];
            }
            #pragma unroll
            for (int nt = 0; nt < 4; nt++) {
                const int nb = wn * 32 + nt * 8;
                bf[nt][0] = Bs[kc + c][(nb + r) ^ s0];
                bf[nt][1] = Bs[kc + c + 4][(nb + r) ^ s1];
            }
            #pragma unroll
            for (int mt = 0; mt < 4; mt++)
                #pragma unroll
                for (int nt = 0; nt < 4; nt++)
                    mma_tf32(acc[mt][nt], af[mt][0], af[mt][1], af[mt][2], af[mt][3],
                             bf[nt][0], bf[nt][1]);
        }
        __syncthreads();
    }

    #pragma unroll
    for (int nt = 0; nt < 4; nt++) {
        const int col = bn + wn * 32 + nt * 8 + 2 * c;
        const float2 bb = *(const float2*)(bias + col);
        #pragma unroll
        for (int mt = 0; mt < 4; mt++) {
            const int row0 = bm + wm * 64 + mt * 16 + r;
            float2 o0 = make_float2(acc[mt][nt][0] + bb.x, acc[mt][nt][1] + bb.y);
            float2 o1 = make_float2(acc[mt][nt][2] + bb.x, acc[mt][nt][3] + bb.y);
            *(float2*)&C[(size_t)row0 * NN + col]       = o0;
            *(float2*)&C[(size_t)(row0 + 8) * NN + col] = o1;
        }
    }
}

// ---------------------------------------------------------------------------
// RoPE in-place on q,k halves of g_qkv.
// ---------------------------------------------------------------------------
__global__ __launch_bounds__(256)
void rope_kernel(const float* __restrict__ cosT, const float* __restrict__ sinT)
{
    int idx = blockIdx.x * blockDim.x + threadIdx.x;
    const int total = SQ * 2 * NH * HALF;
    if (idx >= total) return;
    int d  = idx % HALF;
    int h  = (idx / HALF) % NH;
    int qk = (idx / (HALF * NH)) & 1;
    int s  = idx / (HALF * NH * 2);

    float* base = g_qkv + (size_t)s * QKV3 + qk * EMB + h * HD;
    float x1 = base[d];
    float x2 = base[d + HALF];
    float c  = cosT[(size_t)s * HD + d];
    float sn = sinT[(size_t)s * HD + d];
    base[d]        = x1 * c - x2 * sn;
    base[d + HALF] = x2 * c + x1 * sn;
}

// ---------------------------------------------------------------------------
// Tensor-core block-diagonal varlen flash attention, 3xTF32 split precision.
// S^T = K·Q^T with K,Q split hi/lo (3 mmas); O^T = V^T·P^T with P split (2 mmas).
// grid = (SQ/64, NH), 256 threads.
// ---------------------------------------------------------------------------
#define ATTN_SMEM_BYTES ((4*BQ*QSTR + BK*VSTR + 2*BK*PSTR) * 4 + (64 + 64 + 16) * 4)

__global__ __launch_bounds__(256)
void attn_kernel(const float* __restrict__ qkv, const int* __restrict__ cu,
                 float* __restrict__ out)
{
    extern __shared__ float sm[];
    float* Qh = sm;                       // [64][QSTR] tf32-hi of Q (query, dim)
    float* Ql = Qh + BQ * QSTR;           // [64][QSTR] tf32-lo of Q
    float* Kh = Ql + BQ * QSTR;           // [64][QSTR] tf32-hi of K (key, dim)
    float* Kl = Kh + BK * QSTR;           // [64][QSTR] tf32-lo of K
    float* Vs = Kl + BK * QSTR;           // [64][VSTR] tf32 V (key, dim), 72..79 zero
    float* Ph = Vs + BK * VSTR;           // [64][PSTR] tf32-hi of P^T (key, query)
    float* Pl = Ph + BK * PSTR;           // [64][PSTR] tf32-lo of P^T
    int* segq = (int*)(Pl + BK * PSTR);
    int* segk = segq + 64;
    int* cus  = segk + 64;

    const int tid  = threadIdx.x;
    const int lane = tid & 31;
    const int warp = tid >> 5;
    const int r    = lane >> 2;
    const int cq   = lane & 3;
    const int nb   = warp * 8;
    const int h    = blockIdx.y;
    const int q0   = blockIdx.x * BQ;

    if (tid <= NSEG) cus[tid] = cu[tid];
    __syncthreads();

    if (tid < BQ) {
        int p = q0 + tid;
        int s = 0;
        #pragma unroll
        for (int i = 1; i <= NSEG; i++) s += (p >= cus[i]);
        segq[tid] = s;
    }
    // load Q tile, split hi/lo
    #pragma unroll
    for (int it = 0; it < (BQ * HD) / 256; it++) {
        int idx = tid + it * 256;
        int d = idx % HD, row = idx / HD;
        float x = qkv[(size_t)(q0 + row) * QKV3 + h * HD + d];
        unsigned hb = f2tf32(x);
        float lo = x - __uint_as_float(hb);
        Qh[row * QSTR + d] = __uint_as_float(hb);
        Ql[row * QSTR + d] = __uint_as_float(f2tf32(lo));
    }
    // zero V padding dims 72..79
    #pragma unroll
    for (int i = tid; i < BK * 8; i += 256)
        Vs[(i >> 3) * VSTR + HD + (i & 7)] = 0.0f;
    __syncthreads();

    const int sq0 = segq[nb + 2 * cq];
    const int sq1 = segq[nb + 2 * cq + 1];
    const int k_lo = cus[segq[0]];
    const int k_hi = cus[segq[BQ - 1] + 1];

    float m[2]  = {-1e30f, -1e30f};
    float l[2]  = {0.0f, 0.0f};
    float oa[5][4];
    #pragma unroll
    for (int mt = 0; mt < 5; mt++)
        #pragma unroll
        for (int i = 0; i < 4; i++) oa[mt][i] = 0.0f;

    const float scale = 0.11785113019775793f;  // 1/sqrt(72)

    for (int kk0 = k_lo; kk0 < k_hi; kk0 += BK) {
        // ---- load K (split hi/lo) and V (tf32) tiles ----
        #pragma unroll
        for (int it = 0; it < (BK * HD) / 256; it++) {
            int idx = tid + it * 256;
            int d = idx % HD, ky = idx / HD;
            int key = kk0 + ky;
            float kv = 0.0f, vv = 0.0f;
            if (key < k_hi) {
                const float* row = qkv + (size_t)key * QKV3 + h * HD + d;
                kv = row[EMB];
                vv = row[2 * EMB];
            }
            unsigned hb = f2tf32(kv);
            float lo = kv - __uint_as_float(hb);
            Kh[ky * QSTR + d] = __uint_as_float(hb);
            Kl[ky * QSTR + d] = __uint_as_float(f2tf32(lo));
            Vs[ky * VSTR + d] = __uint_as_float(f2tf32(vv));
        }
        if (tid < BK) {
            int key = kk0 + tid;
            int s = -1;
            if (key < k_hi) {
                s = 0;
                #pragma unroll
                for (int i = 1; i <= NSEG; i++) s += (key >= cus[i]);
            }
            segk[tid] = s;
        }
        __syncthreads();

        // ---- S^T = K·Q^T, 3xTF32: Kh*Qh + Kh*Ql + Kl*Qh ----
        float sf[4][4];
        #pragma unroll
        for (int mt = 0; mt < 4; mt++)
            #pragma unroll
            for (int i = 0; i < 4; i++) sf[mt][i] = 0.0f;

        #pragma unroll
        for (int k0 = 0; k0 < HD; k0 += 8) {
            unsigned bh0 = __float_as_uint(Qh[(nb + r) * QSTR + k0 + cq]);
            unsigned bh1 = __float_as_uint(Qh[(nb + r) * QSTR + k0 + cq + 4]);
            unsigned bl0 = __float_as_uint(Ql[(nb + r) * QSTR + k0 + cq]);
            unsigned bl1 = __float_as_uint(Ql[(nb + r) * QSTR + k0 + cq + 4]);
            #pragma unroll
            for (int mt = 0; mt < 4; mt++) {
                const int kb = mt * 16;
                unsigned ah0 = __float_as_uint(Kh[(kb + r) * QSTR + k0 + cq]);
                unsigned ah1 = __float_as_uint(Kh[(kb + r + 8) * QSTR + k0 + cq]);
                unsigned ah2 = __float_as_uint(Kh[(kb + r) * QSTR + k0 + cq + 4]);
                unsigned ah3 = __float_as_uint(Kh[(kb + r + 8) * QSTR + k0 + cq + 4]);
                unsigned al0 = __float_as_uint(Kl[(kb + r) * QSTR + k0 + cq]);
                unsigned al1 = __float_as_uint(Kl[(kb + r + 8) * QSTR + k0 + cq]);
                unsigned al2 = __float_as_uint(Kl[(kb + r) * QSTR + k0 + cq + 4]);
                unsigned al3 = __float_as_uint(Kl[(kb + r + 8) * QSTR + k0 + cq + 4]);
                mma_tf32(sf[mt], ah0, ah1, ah2, ah3, bh0, bh1);
                mma_tf32(sf[mt], ah0, ah1, ah2, ah3, bl0, bl1);
                mma_tf32(sf[mt], al0, al1, al2, al3, bh0, bh1);
            }
        }

        int skr[4][2];
        #pragma unroll
        for (int mt = 0; mt < 4; mt++) {
            skr[mt][0] = segk[mt * 16 + r];
            skr[mt][1] = segk[mt * 16 + r + 8];
        }

        // ---- online softmax per query column ----
        const int sqv[2] = {sq0, sq1};
        #pragma unroll
        for (int qq = 0; qq < 2; qq++) {
            float mx = -1e30f;
            #pragma unroll
            for (int mt = 0; mt < 4; mt++) {
                float v0 = (skr[mt][0] == sqv[qq]) ? sf[mt][qq] * scale     : -1e30f;
                float v1 = (skr[mt][1] == sqv[qq]) ? sf[mt][qq + 2] * scale : -1e30f;
                sf[mt][qq]     = v0;
                sf[mt][qq + 2] = v1;
                mx = fmaxf(mx, fmaxf(v0, v1));
            }
            mx = fmaxf(mx, __shfl_xor_sync(0xffffffffu, mx, 4));
            mx = fmaxf(mx, __shfl_xor_sync(0xffffffffu, mx, 8));
            mx = fmaxf(mx, __shfl_xor_sync(0xffffffffu, mx, 16));

            float mn  = fmaxf(m[qq], mx);
            float fac = __expf(m[qq] - mn);
            m[qq] = mn;

            float sum = 0.0f;
            #pragma unroll
            for (int mt = 0; mt < 4; mt++) {
                float p0 = (sf[mt][qq]     > -1e29f) ? __expf(sf[mt][qq]     - mn) : 0.0f;
                float p1 = (sf[mt][qq + 2] > -1e29f) ? __expf(sf[mt][qq + 2] - mn) : 0.0f;
                sf[mt][qq]     = p0;
                sf[mt][qq + 2] = p1;
                sum += p0 + p1;
            }
            sum += __shfl_xor_sync(0xffffffffu, sum, 4);
            sum += __shfl_xor_sync(0xffffffffu, sum, 8);
            sum += __shfl_xor_sync(0xffffffffu, sum, 16);
            l[qq] = l[qq] * fac + sum;

            #pragma unroll
            for (int mt = 0; mt < 5; mt++) {
                oa[mt][qq]     *= fac;
                oa[mt][qq + 2] *= fac;
            }
        }

        // ---- stage P^T split hi/lo ----
        #pragma unroll
        for (int mt = 0; mt < 4; mt++) {
            #pragma unroll
            for (int half = 0; half < 2; half++) {
                const int krow = mt * 16 + r + half * 8;
                float p0 = sf[mt][half * 2];
                float p1 = sf[mt][half * 2 + 1];
                unsigned h0 = f2tf32(p0), h1 = f2tf32(p1);
                float l0 = p0 - __uint_as_float(h0);
                float l1 = p1 - __uint_as_float(h1);
                *(float2*)&Ph[krow * PSTR + nb + 2 * cq] =
                    make_float2(__uint_as_float(h0), __uint_as_float(h1));
                *(float2*)&Pl[krow * PSTR + nb + 2 * cq] =
                    make_float2(__uint_as_float(f2tf32(l0)), __uint_as_float(f2tf32(l1)));
            }
        }
        __syncthreads();

        // ---- O^T += V^T·(Ph + Pl) ----
        #pragma unroll
        for (int k0 = 0; k0 < BK; k0 += 8) {
            unsigned bh0 = __float_as_uint(Ph[(k0 + cq) * PSTR + nb + r]);
            unsigned bh1 = __float_as_uint(Ph[(k0 + cq + 4) * PSTR + nb + r]);
            unsigned bl0 = __float_as_uint(Pl[(k0 + cq) * PSTR + nb + r]);
            unsigned bl1 = __float_as_uint(Pl[(k0 + cq + 4) * PSTR + nb + r]);
            #pragma unroll
            for (int mt = 0; mt < 5; mt++) {
                const int db = mt * 16;
                unsigned a0 = __float_as_uint(Vs[(k0 + cq) * VSTR + db + r]);
                unsigned a1 = __float_as_uint(Vs[(k0 + cq) * VSTR + db + r + 8]);
                unsigned a2 = __float_as_uint(Vs[(k0 + cq + 4) * VSTR + db + r]);
                unsigned a3 = __float_as_uint(Vs[(k0 + cq + 4) * VSTR + db + r + 8]);
                mma_tf32(oa[mt], a0, a1, a2, a3, bh0, bh1);
                mma_tf32(oa[mt], a0, a1, a2, a3, bl0, bl1);
            }
        }
        __syncthreads();
    }

    // ---- normalize + store ----
    const float inv0 = 1.0f / l[0];
    const float inv1 = 1.0f / l[1];
    const size_t qa = (size_t)(q0 + nb + 2 * cq);
    const size_t qb = qa + 1;
    #pragma unroll
    for (int mt = 0; mt < 5; mt++) {
        int d0 = mt * 16 + r;
        int d1 = d0 + 8;
        if (d0 < HD) {
            out[qa * EMB + h * HD + d0] = oa[mt][0] * inv0;
            out[qb * EMB + h * HD + d0] = oa[mt][1] * inv1;
        }
        if (d1 < HD) {
            out[qa * EMB + h * HD + d1] = oa[mt][2] * inv0;
            out[qb * EMB + h * HD + d1] = oa[mt][3] * inv1;
        }
    }
}

// ---------------------------------------------------------------------------
extern "C" void kernel_launch(void* const* d_in, const int* in_sizes, int n_in,
                              void* d_out, int out_size)
{
    const float* hidden = (const float*)d_in[0];
    const int*   cu     = (const int*)  d_in[1];
    const float* cosT   = (const float*)d_in[2];
    const float* sinT   = (const float*)d_in[3];
    const float* w_qkv  = (const float*)d_in[4];
    const float* b_qkv  = (const float*)d_in[5];
    const float* w_out  = (const float*)d_in[6];
    const float* b_out  = (const float*)d_in[7];
    float* out = (float*)d_out;

    void* p_qkv = nullptr;
    void* p_attn = nullptr;
    cudaGetSymbolAddress(&p_qkv, g_qkv);
    cudaGetSymbolAddress(&p_attn, g_attn);
    float* qkv  = (float*)p_qkv;
    float* attn = (float*)p_attn;

    // 1) QKV projection (tf32 tensor cores)
    dim3 g1(QKV3 / 128, SQ / 128);
    gemm_tf32<QKV3, EMB><<<g1, 256>>>(hidden, w_qkv, b_qkv, qkv);

    // 2) RoPE on q,k in place
    const int total = SQ * 2 * NH * HALF;
    rope_kernel<<<(total + 255) / 256, 256>>>(cosT, sinT);

    // 3) varlen block-diagonal attention (3xTF32 tensor cores)
    cudaFuncSetAttribute(attn_kernel, cudaFuncAttributeMaxDynamicSharedMemorySize,
                         ATTN_SMEM_BYTES);
    attn_kernel<<<dim3(SQ / BQ, NH), 256, ATTN_SMEM_BYTES>>>(qkv, cu, attn);

    // 4) output projection (tf32 tensor cores)
    dim3 g2(EMB / 128, SQ / 128);
    gemm_tf32<EMB, EMB><<<g2, 256>>>(attn, w_out, b_out, out);
}

// round 6
// speedup vs baseline: 2.1457x; 1.0526x over previous
#include <cuda_runtime.h>
#include <math.h>

#define SQ   4096
#define EMB  1152
#define NH   16
#define HD   72
#define HALF 36
#define NSEG 8
#define QKV3 (3*EMB)

#define BQ 64
#define BK 64

#define QSTR 76   // Q/K hi+lo smem stride (floats)
#define VSTR 88   // V smem stride (80 dims incl. pad)
#define PSTR 72   // P^T smem stride

static __device__ float g_qkv[(size_t)SQ * QKV3];   // (S, 3E) scratch
static __device__ float g_attn[(size_t)SQ * EMB];   // (S, E) attention output

// ---------------------------------------------------------------------------
// TF32 helpers
// ---------------------------------------------------------------------------
__device__ __forceinline__ unsigned f2tf32(float x) {
    unsigned r;
    asm("cvt.rna.tf32.f32 %0, %1;" : "=r"(r) : "f"(x));
    return r;
}

__device__ __forceinline__ void mma_tf32(float c[4],
                                         unsigned a0, unsigned a1, unsigned a2, unsigned a3,
                                         unsigned b0, unsigned b1) {
    asm("mma.sync.aligned.m16n8k8.row.col.f32.tf32.tf32.f32 "
        "{%0,%1,%2,%3}, {%4,%5,%6,%7}, {%8,%9}, {%0,%1,%2,%3};"
        : "+f"(c[0]), "+f"(c[1]), "+f"(c[2]), "+f"(c[3])
        : "r"(a0), "r"(a1), "r"(a2), "r"(a3), "r"(b0), "r"(b1));
}

// ---------------------------------------------------------------------------
// TF32 tensor-core GEMM, software-pipelined + double-buffered smem.
// C[M,N] = A[M,K] * B[N,K]^T + bias[N]
// ---------------------------------------------------------------------------
template<int NN, int KK>
__global__ __launch_bounds__(256)
void gemm_tf32(const float* __restrict__ A, const float* __restrict__ B,
               const float* __restrict__ bias, float* __restrict__ C)
{
    __shared__ unsigned As[2][16][136];
    __shared__ unsigned Bs[2][16][136];

    const int bm   = blockIdx.y * 128;
    const int bn   = blockIdx.x * 128;
    const int tid  = threadIdx.x;
    const int warp = tid >> 5;
    const int lane = tid & 31;
    const int wm   = warp >> 2;
    const int wn   = warp & 3;
    const int r    = lane >> 2;
    const int c    = lane & 3;
    const int lrow = tid >> 2;
    const int lcol = (tid & 3) << 2;

    float acc[4][4][4];
    #pragma unroll
    for (int mt = 0; mt < 4; mt++)
        #pragma unroll
        for (int nt = 0; nt < 4; nt++)
            #pragma unroll
            for (int i = 0; i < 4; i++) acc[mt][nt][i] = 0.0f;

    const float* Aptr = A + (size_t)(bm + lrow) * KK + lcol;
    const float* Bptr = B + (size_t)(bn + lrow) * KK + lcol;

    float4 ga0, ga1, gb0, gb1;
    // prefetch tile 0
    ga0 = *(const float4*)(Aptr);
    ga1 = *(const float4*)(Aptr + (size_t)64 * KK);
    gb0 = *(const float4*)(Bptr);
    gb1 = *(const float4*)(Bptr + (size_t)64 * KK);

    // stage tile 0 into buffer 0
    {
        float av0[4] = {ga0.x, ga0.y, ga0.z, ga0.w};
        float av1[4] = {ga1.x, ga1.y, ga1.z, ga1.w};
        float bv0[4] = {gb0.x, gb0.y, gb0.z, gb0.w};
        float bv1[4] = {gb1.x, gb1.y, gb1.z, gb1.w};
        #pragma unroll
        for (int j = 0; j < 4; j++) {
            int k = lcol + j;
            int s = ((k >> 2) & 3) << 3;
            As[0][k][lrow ^ s]        = f2tf32(av0[j]);
            As[0][k][(lrow + 64) ^ s] = f2tf32(av1[j]);
            Bs[0][k][lrow ^ s]        = f2tf32(bv0[j]);
            Bs[0][k][(lrow + 64) ^ s] = f2tf32(bv1[j]);
        }
    }
    __syncthreads();

    const int NKT = KK / 16;
    for (int kt = 0; kt < NKT; kt++) {
        const int cur = kt & 1;
        // prefetch next tile's gmem into registers (overlaps with compute)
        if (kt + 1 < NKT) {
            const int k0 = (kt + 1) * 16;
            ga0 = *(const float4*)(Aptr + k0);
            ga1 = *(const float4*)(Aptr + (size_t)64 * KK + k0);
            gb0 = *(const float4*)(Bptr + k0);
            gb1 = *(const float4*)(Bptr + (size_t)64 * KK + k0);
        }

        // compute on buffer cur
        #pragma unroll
        for (int kc = 0; kc < 16; kc += 8) {
            const int s0 = ((kc >> 2) & 3) << 3;
            const int s1 = (((kc >> 2) + 1) & 3) << 3;

            unsigned af[4][4], bf[4][2];
            #pragma unroll
            for (int mt = 0; mt < 4; mt++) {
                const int mb = wm * 64 + mt * 16;
                af[mt][0] = As[cur][kc + c][(mb + r) ^ s0];
                af[mt][1] = As[cur][kc + c][(mb + r + 8) ^ s0];
                af[mt][2] = As[cur][kc + c + 4][(mb + r) ^ s1];
                af[mt][3] = As[cur][kc + c + 4][(mb + r + 8) ^ s1];
            }
            #pragma unroll
            for (int nt = 0; nt < 4; nt++) {
                const int nb = wn * 32 + nt * 8;
                bf[nt][0] = Bs[cur][kc + c][(nb + r) ^ s0];
                bf[nt][1] = Bs[cur][kc + c + 4][(nb + r) ^ s1];
            }
            #pragma unroll
            for (int mt = 0; mt < 4; mt++)
                #pragma unroll
                for (int nt = 0; nt < 4; nt++)
                    mma_tf32(acc[mt][nt], af[mt][0], af[mt][1], af[mt][2], af[mt][3],
                             bf[nt][0], bf[nt][1]);
        }

        // stage next tile into the other buffer (no pre-sync needed)
        if (kt + 1 < NKT) {
            const int nxt = cur ^ 1;
            float av0[4] = {ga0.x, ga0.y, ga0.z, ga0.w};
            float av1[4] = {ga1.x, ga1.y, ga1.z, ga1.w};
            float bv0[4] = {gb0.x, gb0.y, gb0.z, gb0.w};
            float bv1[4] = {gb1.x, gb1.y, gb1.z, gb1.w};
            #pragma unroll
            for (int j = 0; j < 4; j++) {
                int k = lcol + j;
                int s = ((k >> 2) & 3) << 3;
                As[nxt][k][lrow ^ s]        = f2tf32(av0[j]);
                As[nxt][k][(lrow + 64) ^ s] = f2tf32(av1[j]);
                Bs[nxt][k][lrow ^ s]        = f2tf32(bv0[j]);
                Bs[nxt][k][(lrow + 64) ^ s] = f2tf32(bv1[j]);
            }
            __syncthreads();
        }
    }

    #pragma unroll
    for (int nt = 0; nt < 4; nt++) {
        const int col = bn + wn * 32 + nt * 8 + 2 * c;
        const float2 bb = *(const float2*)(bias + col);
        #pragma unroll
        for (int mt = 0; mt < 4; mt++) {
            const int row0 = bm + wm * 64 + mt * 16 + r;
            float2 o0 = make_float2(acc[mt][nt][0] + bb.x, acc[mt][nt][1] + bb.y);
            float2 o1 = make_float2(acc[mt][nt][2] + bb.x, acc[mt][nt][3] + bb.y);
            *(float2*)&C[(size_t)row0 * NN + col]       = o0;
            *(float2*)&C[(size_t)(row0 + 8) * NN + col] = o1;
        }
    }
}

// ---------------------------------------------------------------------------
// RoPE in-place on q,k halves of g_qkv.
// ---------------------------------------------------------------------------
__global__ __launch_bounds__(256)
void rope_kernel(const float* __restrict__ cosT, const float* __restrict__ sinT)
{
    int idx = blockIdx.x * blockDim.x + threadIdx.x;
    const int total = SQ * 2 * NH * HALF;
    if (idx >= total) return;
    int d  = idx % HALF;
    int h  = (idx / HALF) % NH;
    int qk = (idx / (HALF * NH)) & 1;
    int s  = idx / (HALF * NH * 2);

    float* base = g_qkv + (size_t)s * QKV3 + qk * EMB + h * HD;
    float x1 = base[d];
    float x2 = base[d + HALF];
    float c  = cosT[(size_t)s * HD + d];
    float sn = sinT[(size_t)s * HD + d];
    base[d]        = x1 * c - x2 * sn;
    base[d + HALF] = x2 * c + x1 * sn;
}

// ---------------------------------------------------------------------------
// Tensor-core block-diagonal varlen flash attention.
// S^T = K·Q^T 3xTF32 (K,Q split hi/lo); O^T = V^T·P^T single tf32 (P rna).
// grid = (SQ/64, NH), 256 threads.
// ---------------------------------------------------------------------------
#define ATTN_SMEM_BYTES ((4*BQ*QSTR + BK*VSTR + BK*PSTR) * 4 + (64 + 64 + 16) * 4)

__global__ __launch_bounds__(256)
void attn_kernel(const float* __restrict__ qkv, const int* __restrict__ cu,
                 float* __restrict__ out)
{
    extern __shared__ float sm[];
    float* Qh = sm;                       // [64][QSTR] tf32-hi of Q (query, dim)
    float* Ql = Qh + BQ * QSTR;           // [64][QSTR] tf32-lo of Q
    float* Kh = Ql + BQ * QSTR;           // [64][QSTR] tf32-hi of K (key, dim)
    float* Kl = Kh + BK * QSTR;           // [64][QSTR] tf32-lo of K
    float* Vs = Kl + BK * QSTR;           // [64][VSTR] tf32 V (key, dim), 72..79 zero
    float* Ps = Vs + BK * VSTR;           // [64][PSTR] tf32 P^T (key, query)
    int* segq = (int*)(Ps + BK * PSTR);
    int* segk = segq + 64;
    int* cus  = segk + 64;

    const int tid  = threadIdx.x;
    const int lane = tid & 31;
    const int warp = tid >> 5;
    const int r    = lane >> 2;
    const int cq   = lane & 3;
    const int nb   = warp * 8;
    const int h    = blockIdx.y;
    const int q0   = blockIdx.x * BQ;

    if (tid <= NSEG) cus[tid] = cu[tid];
    __syncthreads();

    if (tid < BQ) {
        int p = q0 + tid;
        int s = 0;
        #pragma unroll
        for (int i = 1; i <= NSEG; i++) s += (p >= cus[i]);
        segq[tid] = s;
    }
    // load Q tile, split hi/lo
    #pragma unroll
    for (int it = 0; it < (BQ * HD) / 256; it++) {
        int idx = tid + it * 256;
        int d = idx % HD, row = idx / HD;
        float x = qkv[(size_t)(q0 + row) * QKV3 + h * HD + d];
        unsigned hb = f2tf32(x);
        float lo = x - __uint_as_float(hb);
        Qh[row * QSTR + d] = __uint_as_float(hb);
        Ql[row * QSTR + d] = __uint_as_float(f2tf32(lo));
    }
    // zero V padding dims 72..79
    #pragma unroll
    for (int i = tid; i < BK * 8; i += 256)
        Vs[(i >> 3) * VSTR + HD + (i & 7)] = 0.0f;
    __syncthreads();

    const int sq0 = segq[nb + 2 * cq];
    const int sq1 = segq[nb + 2 * cq + 1];
    const int k_lo = cus[segq[0]];
    const int k_hi = cus[segq[BQ - 1] + 1];

    float m[2]  = {-1e30f, -1e30f};
    float l[2]  = {0.0f, 0.0f};
    float oa[5][4];
    #pragma unroll
    for (int mt = 0; mt < 5; mt++)
        #pragma unroll
        for (int i = 0; i < 4; i++) oa[mt][i] = 0.0f;

    const float scale = 0.11785113019775793f;  // 1/sqrt(72)

    for (int kk0 = k_lo; kk0 < k_hi; kk0 += BK) {
        // ---- load K (split hi/lo) and V (tf32) tiles ----
        #pragma unroll
        for (int it = 0; it < (BK * HD) / 256; it++) {
            int idx = tid + it * 256;
            int d = idx % HD, ky = idx / HD;
            int key = kk0 + ky;
            float kv = 0.0f, vv = 0.0f;
            if (key < k_hi) {
                const float* row = qkv + (size_t)key * QKV3 + h * HD + d;
                kv = row[EMB];
                vv = row[2 * EMB];
            }
            unsigned hb = f2tf32(kv);
            float lo = kv - __uint_as_float(hb);
            Kh[ky * QSTR + d] = __uint_as_float(hb);
            Kl[ky * QSTR + d] = __uint_as_float(f2tf32(lo));
            Vs[ky * VSTR + d] = __uint_as_float(f2tf32(vv));
        }
        if (tid < BK) {
            int key = kk0 + tid;
            int s = -1;
            if (key < k_hi) {
                s = 0;
                #pragma unroll
                for (int i = 1; i <= NSEG; i++) s += (key >= cus[i]);
            }
            segk[tid] = s;
        }
        __syncthreads();

        // ---- S^T = K·Q^T, 3xTF32: Kh*Qh + Kh*Ql + Kl*Qh ----
        float sf[4][4];
        #pragma unroll
        for (int mt = 0; mt < 4; mt++)
            #pragma unroll
            for (int i = 0; i < 4; i++) sf[mt][i] = 0.0f;

        #pragma unroll
        for (int k0 = 0; k0 < HD; k0 += 8) {
            unsigned bh0 = __float_as_uint(Qh[(nb + r) * QSTR + k0 + cq]);
            unsigned bh1 = __float_as_uint(Qh[(nb + r) * QSTR + k0 + cq + 4]);
            unsigned bl0 = __float_as_uint(Ql[(nb + r) * QSTR + k0 + cq]);
            unsigned bl1 = __float_as_uint(Ql[(nb + r) * QSTR + k0 + cq + 4]);
            #pragma unroll
            for (int mt = 0; mt < 4; mt++) {
                const int kb = mt * 16;
                unsigned ah0 = __float_as_uint(Kh[(kb + r) * QSTR + k0 + cq]);
                unsigned ah1 = __float_as_uint(Kh[(kb + r + 8) * QSTR + k0 + cq]);
                unsigned ah2 = __float_as_uint(Kh[(kb + r) * QSTR + k0 + cq + 4]);
                unsigned ah3 = __float_as_uint(Kh[(kb + r + 8) * QSTR + k0 + cq + 4]);
                unsigned al0 = __float_as_uint(Kl[(kb + r) * QSTR + k0 + cq]);
                unsigned al1 = __float_as_uint(Kl[(kb + r + 8) * QSTR + k0 + cq]);
                unsigned al2 = __float_as_uint(Kl[(kb + r) * QSTR + k0 + cq + 4]);
                unsigned al3 = __float_as_uint(Kl[(kb + r + 8) * QSTR + k0 + cq + 4]);
                mma_tf32(sf[mt], ah0, ah1, ah2, ah3, bh0, bh1);
                mma_tf32(sf[mt], ah0, ah1, ah2, ah3, bl0, bl1);
                mma_tf32(sf[mt], al0, al1, al2, al3, bh0, bh1);
            }
        }

        int skr[4][2];
        #pragma unroll
        for (int mt = 0; mt < 4; mt++) {
            skr[mt][0] = segk[mt * 16 + r];
            skr[mt][1] = segk[mt * 16 + r + 8];
        }

        // ---- online softmax per query column ----
        const int sqv[2] = {sq0, sq1};
        #pragma unroll
        for (int qq = 0; qq < 2; qq++) {
            float mx = -1e30f;
            #pragma unroll
            for (int mt = 0; mt < 4; mt++) {
                float v0 = (skr[mt][0] == sqv[qq]) ? sf[mt][qq] * scale     : -1e30f;
                float v1 = (skr[mt][1] == sqv[qq]) ? sf[mt][qq + 2] * scale : -1e30f;
                sf[mt][qq]     = v0;
                sf[mt][qq + 2] = v1;
                mx = fmaxf(mx, fmaxf(v0, v1));
            }
            mx = fmaxf(mx, __shfl_xor_sync(0xffffffffu, mx, 4));
            mx = fmaxf(mx, __shfl_xor_sync(0xffffffffu, mx, 8));
            mx = fmaxf(mx, __shfl_xor_sync(0xffffffffu, mx, 16));

            float mn  = fmaxf(m[qq], mx);
            float fac = __expf(m[qq] - mn);
            m[qq] = mn;

            float sum = 0.0f;
            #pragma unroll
            for (int mt = 0; mt < 4; mt++) {
                float p0 = (sf[mt][qq]     > -1e29f) ? __expf(sf[mt][qq]     - mn) : 0.0f;
                float p1 = (sf[mt][qq + 2] > -1e29f) ? __expf(sf[mt][qq + 2] - mn) : 0.0f;
                sf[mt][qq]     = p0;
                sf[mt][qq + 2] = p1;
                sum += p0 + p1;
            }
            sum += __shfl_xor_sync(0xffffffffu, sum, 4);
            sum += __shfl_xor_sync(0xffffffffu, sum, 8);
            sum += __shfl_xor_sync(0xffffffffu, sum, 16);
            l[qq] = l[qq] * fac + sum;

            #pragma unroll
            for (int mt = 0; mt < 5; mt++) {
                oa[mt][qq]     *= fac;
                oa[mt][qq + 2] *= fac;
            }
        }

        // ---- stage P^T (rna tf32) ----
        #pragma unroll
        for (int mt = 0; mt < 4; mt++) {
            #pragma unroll
            for (int half = 0; half < 2; half++) {
                const int krow = mt * 16 + r + half * 8;
                unsigned h0 = f2tf32(sf[mt][half * 2]);
                unsigned h1 = f2tf32(sf[mt][half * 2 + 1]);
                *(float2*)&Ps[krow * PSTR + nb + 2 * cq] =
                    make_float2(__uint_as_float(h0), __uint_as_float(h1));
            }
        }
        __syncthreads();

        // ---- O^T += V^T·P^T ----
        #pragma unroll
        for (int k0 = 0; k0 < BK; k0 += 8) {
            unsigned b0 = __float_as_uint(Ps[(k0 + cq) * PSTR + nb + r]);
            unsigned b1 = __float_as_uint(Ps[(k0 + cq + 4) * PSTR + nb + r]);
            #pragma unroll
            for (int mt = 0; mt < 5; mt++) {
                const int db = mt * 16;
                unsigned a0 = __float_as_uint(Vs[(k0 + cq) * VSTR + db + r]);
                unsigned a1 = __float_as_uint(Vs[(k0 + cq) * VSTR + db + r + 8]);
                unsigned a2 = __float_as_uint(Vs[(k0 + cq + 4) * VSTR + db + r]);
                unsigned a3 = __float_as_uint(Vs[(k0 + cq + 4) * VSTR + db + r + 8]);
                mma_tf32(oa[mt], a0, a1, a2, a3, b0, b1);
            }
        }
        __syncthreads();
    }

    // ---- normalize + store ----
    const float inv0 = 1.0f / l[0];
    const float inv1 = 1.0f / l[1];
    const size_t qa = (size_t)(q0 + nb + 2 * cq);
    const size_t qb = qa + 1;
    #pragma unroll
    for (int mt = 0; mt < 5; mt++) {
        int d0 = mt * 16 + r;
        int d1 = d0 + 8;
        if (d0 < HD) {
            out[qa * EMB + h * HD + d0] = oa[mt][0] * inv0;
            out[qb * EMB + h * HD + d0] = oa[mt][1] * inv1;
        }
        if (d1 < HD) {
            out[qa * EMB + h * HD + d1] = oa[mt][2] * inv0;
            out[qb * EMB + h * HD + d1] = oa[mt][3] * inv1;
        }
    }
}

// ---------------------------------------------------------------------------
extern "C" void kernel_launch(void* const* d_in, const int* in_sizes, int n_in,
                              void* d_out, int out_size)
{
    const float* hidden = (const float*)d_in[0];
    const int*   cu     = (const int*)  d_in[1];
    const float* cosT   = (const float*)d_in[2];
    const float* sinT   = (const float*)d_in[3];
    const float* w_qkv  = (const float*)d_in[4];
    const float* b_qkv  = (const float*)d_in[5];
    const float* w_out  = (const float*)d_in[6];
    const float* b_out  = (const float*)d_in[7];
    float* out = (float*)d_out;

    void* p_qkv = nullptr;
    void* p_attn = nullptr;
    cudaGetSymbolAddress(&p_qkv, g_qkv);
    cudaGetSymbolAddress(&p_attn, g_attn);
    float* qkv  = (float*)p_qkv;
    float* attn = (float*)p_attn;

    // 1) QKV projection (tf32 tensor cores, pipelined)
    dim3 g1(QKV3 / 128, SQ / 128);
    gemm_tf32<QKV3, EMB><<<g1, 256>>>(hidden, w_qkv, b_qkv, qkv);

    // 2) RoPE on q,k in place
    const int total = SQ * 2 * NH * HALF;
    rope_kernel<<<(total + 255) / 256, 256>>>(cosT, sinT);

    // 3) varlen block-diagonal attention (3xTF32 S, 1x PV)
    cudaFuncSetAttribute(attn_kernel, cudaFuncAttributeMaxDynamicSharedMemorySize,
                         ATTN_SMEM_BYTES);
    attn_kernel<<<dim3(SQ / BQ, NH), 256, ATTN_SMEM_BYTES>>>(qkv, cu, attn);

    // 4) output projection (tf32 tensor cores, pipelined)
    dim3 g2(EMB / 128, SQ / 128);
    gemm_tf32<EMB, EMB><<<g2, 256>>>(attn, w_out, b_out, out);
}